// round 4
// baseline (speedup 1.0000x reference)
#include <cuda_runtime.h>

#define B_  8
#define H_  224
#define W_  224
#define C_  192
#define QT  4        // q positions per block
#define PAIRS 32     // channel pairs (threadIdx.x)
#define QTH  4       // q threads (threadIdx.y)
#define NTHREADS 128
#define RH  56       // output rows per block
#define ROWSZ (W_ * C_)
#define IMGSZ (H_ * W_ * C_)

typedef unsigned long long u64;

__device__ __forceinline__ void fma2(u64 &d, u64 a, u64 b) {
    asm("fma.rn.f32x2 %0, %1, %2, %0;" : "+l"(d) : "l"(a), "l"(b));
}
__device__ __forceinline__ u64 pack2(float lo, float hi) {
    return (u64)__float_as_uint(lo) | ((u64)__float_as_uint(hi) << 32);
}
__device__ __forceinline__ u64 ldg2(const float* p) {
    u64 v;
    asm("ld.global.nc.b64 %0, [%1];" : "=l"(v) : "l"(p));
    return v;
}

// One pipeline step at global step index t (input row r = p0-3+t):
//  - prefetch row t+2 into WN (slot freed at step t-1)  [distance-2 prefetch]
//  - 49 packed FMAs from WC into static acc slots (T7 = t % 7 compile-time)
//  - output row p = p0-6+t completes in slot (T7+2)%7: store (main only), zero
#define STEP(WC, WN, T7, DOSTORE) do {                                        \
    _Pragma("unroll")                                                         \
    for (int d = 0; d < 7; ++d) WN[d] = ldg2(rowPtr + qcol[d]);               \
    rowPtr += ROWSZ; ++rpre;                                                  \
    if (rpre == H_) { rpre = 0; rowPtr -= IMGSZ; }                            \
    _Pragma("unroll")                                                         \
    for (int i = 0; i < 7; ++i) {                                             \
        const int s = ((T7) + i + 2) % 7;                                     \
        _Pragma("unroll")                                                     \
        for (int j = 0; j < 7; ++j)                                           \
            fma2(acc[s], kreg[i * 7 + j], WC[6 - j]);                         \
    }                                                                         \
    {                                                                         \
        const int so = ((T7) + 2) % 7;                                        \
        if (DOSTORE) {                                                        \
            *(u64*)(out + outOff) = acc[so];                                  \
            outOff += ROWSZ;                                                  \
        }                                                                     \
        acc[so] = 0ULL;                                                       \
    }                                                                         \
} while (0)

// 21-step group (lcm(3,7)): buffer phase and T7 both repeat every 21 steps.
// Starts at t with t%3==0, t%7==6.
#define GROUP21()                                                             \
    STEP(w0, w2, 6, 1); STEP(w1, w0, 0, 1); STEP(w2, w1, 1, 1);               \
    STEP(w0, w2, 2, 1); STEP(w1, w0, 3, 1); STEP(w2, w1, 4, 1);               \
    STEP(w0, w2, 5, 1); STEP(w1, w0, 6, 1); STEP(w2, w1, 0, 1);               \
    STEP(w0, w2, 1, 1); STEP(w1, w0, 2, 1); STEP(w2, w1, 3, 1);               \
    STEP(w0, w2, 4, 1); STEP(w1, w0, 5, 1); STEP(w2, w1, 6, 1);               \
    STEP(w0, w2, 0, 1); STEP(w1, w0, 1, 1); STEP(w2, w1, 2, 1);               \
    STEP(w0, w2, 3, 1); STEP(w1, w0, 4, 1); STEP(w2, w1, 5, 1)

__global__ void __launch_bounds__(NTHREADS, 3)
dwconv_direct(const float* __restrict__ x, const float* __restrict__ kern,
              float* __restrict__ out)
{
    const int tx = threadIdx.x;            // channel pair 0..31
    const int ty = threadIdx.y;            // q 0..3
    const int wt = blockIdx.x;             // 0..55
    const int ht = blockIdx.y;             // 0..3
    const int bz = blockIdx.z;             // 0..23
    const int b  = bz / 3;
    const int g  = bz % 3;

    const int qOut = wt * QT + ty;
    const int p0   = ht * RH;              // p0 % 7 == 0 (RH = 56)
    const int c0   = g * 64 + 2 * tx;

    // ---- 49 kernel taps for this channel pair -> registers (f32x2) ----
    u64 kreg[49];
    #pragma unroll
    for (int t = 0; t < 49; ++t)
        kreg[t] = pack2(kern[c0 * 49 + t], kern[(c0 + 1) * 49 + t]);

    // ---- column offsets for the 7-wide window of this q ----
    int qcol[7];
    #pragma unroll
    for (int d = 0; d < 7; ++d) {
        int q = qOut + d - 3;
        q += (q < 0) ? W_ : 0;
        q -= (q >= W_) ? W_ : 0;
        qcol[d] = q * C_ + c0;
    }

    // row cursor (circular over H)
    int rpre = p0 - 3;
    if (rpre < 0) rpre += H_;
    const float* rowPtr = x + b * IMGSZ + rpre * ROWSZ;

    // 3 register window buffers, distance-2 prefetch
    u64 w0[7], w1[7], w2[7];
    #pragma unroll
    for (int d = 0; d < 7; ++d) w0[d] = ldg2(rowPtr + qcol[d]);   // row t=0
    rowPtr += ROWSZ; ++rpre; if (rpre == H_) { rpre = 0; rowPtr -= IMGSZ; }
    #pragma unroll
    for (int d = 0; d < 7; ++d) w1[d] = ldg2(rowPtr + qcol[d]);   // row t=1
    rowPtr += ROWSZ; ++rpre; if (rpre == H_) { rpre = 0; rowPtr -= IMGSZ; }

    // 7 rolling accumulators (static slots), f32x2
    u64 acc[7];
    #pragma unroll
    for (int m = 0; m < 7; ++m) acc[m] = 0ULL;

    int outOff = ((b * H_ + p0) * W_ + qOut) * C_ + c0;

    // ---- warm-up: t = 0..5 (no stores) ----
    STEP(w0, w2, 0, 0);
    STEP(w1, w0, 1, 0);
    STEP(w2, w1, 2, 0);
    STEP(w0, w2, 3, 0);
    STEP(w1, w0, 4, 0);
    STEP(w2, w1, 5, 0);

    // ---- main: t = 6..47, two 21-step groups (I$-resident hot loop) ----
    #pragma unroll 1
    for (int o = 0; o < 2; ++o) {
        GROUP21();
    }

    // ---- tail: t = 48..61, first 14 entries of the 21-pattern ----
    STEP(w0, w2, 6, 1); STEP(w1, w0, 0, 1); STEP(w2, w1, 1, 1);
    STEP(w0, w2, 2, 1); STEP(w1, w0, 3, 1); STEP(w2, w1, 4, 1);
    STEP(w0, w2, 5, 1); STEP(w1, w0, 6, 1); STEP(w2, w1, 0, 1);
    STEP(w0, w2, 1, 1); STEP(w1, w0, 2, 1); STEP(w2, w1, 3, 1);
    STEP(w0, w2, 4, 1); STEP(w1, w0, 5, 1);
}

extern "C" void kernel_launch(void* const* d_in, const int* in_sizes, int n_in,
                              void* d_out, int out_size) {
    const float* x    = (const float*)d_in[0];   // (8,224,224,192) fp32
    const float* kern = (const float*)d_in[1];   // (192,7,7) fp32
    float* out        = (float*)d_out;           // (8,224,224,192) fp32

    dim3 grid(W_ / QT, H_ / RH, B_ * 3);  // 56 x 4 x 24 = 5376 blocks
    dim3 block(PAIRS, QTH, 1);            // 128 threads
    dwconv_direct<<<grid, block>>>(x, kern, out);
}

// round 5
// speedup vs baseline: 3.0632x; 3.0632x over previous
#include <cuda_runtime.h>
#include <cstdint>

#define B_  8
#define H_  224
#define W_  224
#define C_  192
#define QT  8        // q positions per block
#define NQ  2        // q per thread
#define PAIRS 32     // channel pairs (threadIdx.x)
#define QTH  4       // q-thread groups (threadIdx.y)
#define NTHREADS 128
#define RH  56       // output rows per block
#define SROW 14      // staged columns per row (QT + 6)
#define STAGES 7
#define STAGE_BYTES (SROW * 64 * 4)   // 3584 B per stage
#define ROWSZ (W_ * C_)
#define IMGSZ (H_ * W_ * C_)

typedef unsigned long long u64;

__device__ __forceinline__ void fma2(u64 &d, u64 a, u64 b) {
    asm("fma.rn.f32x2 %0, %1, %2, %0;" : "+l"(d) : "l"(a), "l"(b));
}
__device__ __forceinline__ u64 pack2(float lo, float hi) {
    return (u64)__float_as_uint(lo) | ((u64)__float_as_uint(hi) << 32);
}
__device__ __forceinline__ void cpasync16(uint32_t dst, const float* src) {
    asm volatile("cp.async.cg.shared.global [%0], [%1], 16;" :: "r"(dst), "l"(src));
}
__device__ __forceinline__ void cp_commit() {
    asm volatile("cp.async.commit_group;" ::: "memory");
}
__device__ __forceinline__ void cp_wait3() {
    asm volatile("cp.async.wait_group 3;" ::: "memory");
}
__device__ __forceinline__ uint32_t smem_u32(const void* p) {
    uint32_t a;
    asm("{ .reg .u64 t; cvta.to.shared.u64 t, %1; cvt.u32.u64 %0, t; }" : "=r"(a) : "l"(p));
    return a;
}

// One pipeline step at global step index t (consumes input row r = p0-3+t):
//  - wait depth-4 cp.async group (row t complete), barrier for visibility
//  - 8 LDS.64 window + 98 packed FMAs into static acc slots (T7 = t % 7)
//  - output row completes in slot (T7+2)%7: store (main only), then zero
//  - issue cp.async for row t+4 into stage (T7+4)%7 (after barrier: no WAR hazard)
#define STEP(T7, DOSTORE) do {                                                \
    cp_wait3();                                                               \
    __syncthreads();                                                          \
    u64 w[8];                                                                 \
    _Pragma("unroll")                                                         \
    for (int d = 0; d < 8; ++d)                                               \
        w[d] = *(const u64*)&sbuf[T7][ty * NQ + d][2 * tx];                   \
    _Pragma("unroll")                                                         \
    for (int i = 0; i < 7; ++i) {                                             \
        const int s = ((T7) + i + 2) % 7;                                     \
        _Pragma("unroll")                                                     \
        for (int j = 0; j < 7; ++j) {                                         \
            const u64 kv = kreg[i * 7 + j];                                   \
            fma2(acc[s][0], kv, w[6 - j]);                                    \
            fma2(acc[s][1], kv, w[7 - j]);                                    \
        }                                                                     \
    }                                                                         \
    {                                                                         \
        const int so = ((T7) + 2) % 7;                                        \
        if (DOSTORE) {                                                        \
            *(u64*)(out + outOff)      = acc[so][0];                          \
            *(u64*)(out + outOff + C_) = acc[so][1];                          \
            outOff += ROWSZ;                                                  \
        }                                                                     \
        acc[so][0] = 0ULL; acc[so][1] = 0ULL;                                 \
    }                                                                         \
    {                                                                         \
        const uint32_t dstStage = sdst + (((T7) + 4) % 7) * STAGE_BYTES;      \
        cpasync16(dstStage, rowPtr + colOff0);                                \
        if (has1) cpasync16(dstStage + 2048, rowPtr + colOff1);               \
        cp_commit();                                                          \
        rowPtr += ROWSZ; ++rpre;                                              \
        if (rpre == H_) { rpre = 0; rowPtr -= IMGSZ; }                        \
    }                                                                         \
} while (0)

// 7-step unrolled group starting at t%7 == 6 (period aligns stage & acc phase)
#define GROUP7()                                                              \
    STEP(6, 1); STEP(0, 1); STEP(1, 1); STEP(2, 1);                           \
    STEP(3, 1); STEP(4, 1); STEP(5, 1)

__global__ void __launch_bounds__(NTHREADS, 3)
dwconv_pipe(const float* __restrict__ x, const float* __restrict__ kern,
            float* __restrict__ out)
{
    __shared__ float sbuf[STAGES][SROW][64];   // 24,528 B (7-stage ring)

    const int tx  = threadIdx.x;           // channel pair 0..31
    const int ty  = threadIdx.y;           // q group 0..3
    const int tid = ty * PAIRS + tx;

    const int wt = blockIdx.x;              // 0..27
    const int ht = blockIdx.y;              // 0..3
    const int bz = blockIdx.z;              // 0..23
    const int b  = bz / 3;
    const int g  = bz % 3;

    const int qbase = wt * QT;
    const int p0    = ht * RH;              // p0 % 7 == 0
    const int cbase = g * 64;
    const int c0    = cbase + 2 * tx;

    // ---- 49 kernel taps for this channel pair -> registers (f32x2) ----
    u64 kreg[49];
    #pragma unroll
    for (int t = 0; t < 49; ++t)
        kreg[t] = pack2(kern[c0 * 49 + t], kern[(c0 + 1) * 49 + t]);

    // ---- cp.async staging plan: 224 float4 per stage, threads 0..95 take 2 ----
    const int s0 = tid >> 4, v0 = tid & 15;             // cols 0..7
    const bool has1 = tid < 96;
    const int s1 = (tid + 128) >> 4, v1 = tid & 15;     // cols 8..13
    int qg0 = qbase - 3 + s0; qg0 += (qg0 < 0) ? W_ : 0; qg0 -= (qg0 >= W_) ? W_ : 0;
    int qg1 = qbase - 3 + s1; qg1 += (qg1 < 0) ? W_ : 0; qg1 -= (qg1 >= W_) ? W_ : 0;
    const int colOff0 = qg0 * C_ + cbase + v0 * 4;
    const int colOff1 = qg1 * C_ + cbase + v1 * 4;
    // dst within a stage: col*256B + v*16B   (second col is s0+8 -> +2048B)
    const uint32_t sdst = smem_u32(&sbuf[0][0][0]) + (uint32_t)(s0 * 256 + v0 * 16);

    // row cursor (circular over H)
    int rpre = p0 - 3;
    if (rpre < 0) rpre += H_;
    const float* rowPtr = x + b * IMGSZ + rpre * ROWSZ;

    // ---- prologue: fill stages 0..3 (depth-4), one commit group per row ----
    #pragma unroll
    for (int pr = 0; pr < 4; ++pr) {
        const uint32_t dstStage = sdst + pr * STAGE_BYTES;
        cpasync16(dstStage, rowPtr + colOff0);
        if (has1) cpasync16(dstStage + 2048, rowPtr + colOff1);
        cp_commit();
        rowPtr += ROWSZ; ++rpre;
        if (rpre == H_) { rpre = 0; rowPtr -= IMGSZ; }
    }

    // 7 rolling accumulators (static slots), f32x2 x NQ
    u64 acc[7][2];
    #pragma unroll
    for (int m = 0; m < 7; ++m) { acc[m][0] = 0ULL; acc[m][1] = 0ULL; }

    const int qOut = qbase + ty * NQ;
    int outOff = ((b * H_ + p0) * W_ + qOut) * C_ + c0;

    // ---- warm-up: t = 0..5 (no stores) ----
    STEP(0, 0); STEP(1, 0); STEP(2, 0);
    STEP(3, 0); STEP(4, 0); STEP(5, 0);

    // ---- main: t = 6..61, eight 7-step groups (I$-resident) ----
    #pragma unroll 1
    for (int o = 0; o < 8; ++o) {
        GROUP7();
    }
}

extern "C" void kernel_launch(void* const* d_in, const int* in_sizes, int n_in,
                              void* d_out, int out_size) {
    const float* x    = (const float*)d_in[0];   // (8,224,224,192) fp32
    const float* kern = (const float*)d_in[1];   // (192,7,7) fp32
    float* out        = (float*)d_out;           // (8,224,224,192) fp32

    dim3 grid(W_ / QT, H_ / RH, B_ * 3);  // 28 x 4 x 24 = 2688 blocks
    dim3 block(PAIRS, QTH, 1);            // 128 threads
    dwconv_pipe<<<grid, block>>>(x, kern, out);
}

// round 6
// speedup vs baseline: 3.1814x; 1.0386x over previous
#include <cuda_runtime.h>
#include <cstdint>

#define B_  8
#define H_  224
#define W_  224
#define C_  192
#define QT  8        // q positions per block
#define NQ  2        // q per thread
#define PAIRS 32     // channel pairs (threadIdx.x)
#define QTH  4       // q-thread groups (threadIdx.y)
#define NTHREADS 128
#define RH  56       // output rows per block
#define SROW 14      // staged columns per row (QT + 6)
#define STAGES 8
#define STAGE_BYTES (SROW * 64 * 4)          // 3584 B per stage
#define RING_BYTES  (STAGES * STAGE_BYTES)   // 28672 B
#define ROWSZ (W_ * C_)
#define IMGSZ (H_ * W_ * C_)

typedef unsigned long long u64;

__device__ __forceinline__ void fma2(u64 &d, u64 a, u64 b) {
    asm("fma.rn.f32x2 %0, %1, %2, %0;" : "+l"(d) : "l"(a), "l"(b));
}
__device__ __forceinline__ u64 pack2(float lo, float hi) {
    return (u64)__float_as_uint(lo) | ((u64)__float_as_uint(hi) << 32);
}
__device__ __forceinline__ void cpasync16(uint32_t dst, const float* src) {
    asm volatile("cp.async.cg.shared.global [%0], [%1], 16;" :: "r"(dst), "l"(src));
}
__device__ __forceinline__ void cp_commit() {
    asm volatile("cp.async.commit_group;" ::: "memory");
}
__device__ __forceinline__ void cp_wait2() {
    asm volatile("cp.async.wait_group 2;" ::: "memory");
}
__device__ __forceinline__ uint32_t smem_u32(const void* p) {
    uint32_t a;
    asm("{ .reg .u64 t; cvta.to.shared.u64 t, %1; cvt.u32.u64 %0, t; }" : "=r"(a) : "l"(p));
    return a;
}

// Compute half-step at row phase T7 (t % 7), consuming the stage at byte
// offset SOFF: 8 LDS.64 window + 98 packed FMAs; slot (T7+2)%7 completes.
#define STEP_COMPUTE(T7, SOFF, DOSTORE) do {                                  \
    const char* sb = (const char*)sbuf + (SOFF) + ty * (NQ * 256) + tx * 8;   \
    u64 w[8];                                                                 \
    _Pragma("unroll")                                                         \
    for (int d = 0; d < 8; ++d)                                               \
        w[d] = *(const u64*)(sb + d * 256);                                   \
    _Pragma("unroll")                                                         \
    for (int i = 0; i < 7; ++i) {                                             \
        const int s = ((T7) + i + 2) % 7;                                     \
        _Pragma("unroll")                                                     \
        for (int j = 0; j < 7; ++j) {                                         \
            const u64 kv = kreg[i * 7 + j];                                   \
            fma2(acc[s][0], kv, w[6 - j]);                                    \
            fma2(acc[s][1], kv, w[7 - j]);                                    \
        }                                                                     \
    }                                                                         \
    {                                                                         \
        const int so = ((T7) + 2) % 7;                                        \
        if (DOSTORE) {                                                        \
            *(u64*)(out + outOff)      = acc[so][0];                          \
            *(u64*)(out + outOff + C_) = acc[so][1];                          \
            outOff += ROWSZ;                                                  \
        }                                                                     \
        acc[so][0] = 0ULL; acc[so][1] = 0ULL;                                 \
    }                                                                         \
} while (0)

// Macro step: one wait + one barrier + one commit group for TWO rows.
//  - wait_group 2: rows 2m, 2m+1 have landed (6 rows in flight max, ring=8)
//  - prefetch rows 2m+6, 2m+7 into ring (issued before FMAs for max overlap)
//  - two compute half-steps
#define MACRO2(T7a, T7b, DOSTORE) do {                                        \
    cp_wait2();                                                               \
    __syncthreads();                                                          \
    {                                                                         \
        const uint32_t dA = sdst + offP;                                      \
        cpasync16(dA, rowPtr + colOff0);                                      \
        if (has1) cpasync16(dA + 2048, rowPtr + colOff1);                     \
        rowPtr += ROWSZ; if (rowPtr >= xEnd) rowPtr -= IMGSZ;                 \
        uint32_t p2 = offP + STAGE_BYTES;                                     \
        if (p2 >= RING_BYTES) p2 -= RING_BYTES;                               \
        const uint32_t dB = sdst + p2;                                        \
        cpasync16(dB, rowPtr + colOff0);                                      \
        if (has1) cpasync16(dB + 2048, rowPtr + colOff1);                     \
        rowPtr += ROWSZ; if (rowPtr >= xEnd) rowPtr -= IMGSZ;                 \
        cp_commit();                                                          \
        offP += 2 * STAGE_BYTES; if (offP >= RING_BYTES) offP -= RING_BYTES;  \
    }                                                                         \
    STEP_COMPUTE(T7a, offCa, DOSTORE);                                        \
    offCa += 2 * STAGE_BYTES; if (offCa >= RING_BYTES) offCa -= RING_BYTES;   \
    STEP_COMPUTE(T7b, offCb, DOSTORE);                                        \
    offCb += 2 * STAGE_BYTES; if (offCb >= RING_BYTES) offCb -= RING_BYTES;   \
} while (0)

// 7 macro steps = 14 rows: both acc phase (mod 7) and ring phase (mod 8,
// step 2 -> dynamic offsets) repeat. Starts at t%7 == 6.
#define GROUP7M()                                                             \
    MACRO2(6, 0, 1); MACRO2(1, 2, 1); MACRO2(3, 4, 1); MACRO2(5, 6, 1);       \
    MACRO2(0, 1, 1); MACRO2(2, 3, 1); MACRO2(4, 5, 1)

__global__ void __launch_bounds__(NTHREADS, 3)
dwconv_pipe2(const float* __restrict__ x, const float* __restrict__ kern,
             float* __restrict__ out)
{
    __shared__ float sbuf[STAGES][SROW][64];   // 28,672 B (8-stage ring)

    const int tx  = threadIdx.x;           // channel pair 0..31
    const int ty  = threadIdx.y;           // q group 0..3
    const int tid = ty * PAIRS + tx;

    const int wt = blockIdx.x;              // 0..27
    const int ht = blockIdx.y;              // 0..3
    const int bz = blockIdx.z;              // 0..23
    const int b  = bz / 3;
    const int g  = bz % 3;

    const int qbase = wt * QT;
    const int p0    = ht * RH;              // p0 % 7 == 0
    const int cbase = g * 64;
    const int c0    = cbase + 2 * tx;

    // ---- 49 kernel taps for this channel pair -> registers (f32x2) ----
    u64 kreg[49];
    #pragma unroll
    for (int t = 0; t < 49; ++t)
        kreg[t] = pack2(kern[c0 * 49 + t], kern[(c0 + 1) * 49 + t]);

    // ---- cp.async staging plan: 224 float4 per stage, threads 0..95 take 2 ----
    const int s0 = tid >> 4, v0 = tid & 15;             // cols 0..7
    const bool has1 = tid < 96;
    const int s1 = (tid + 128) >> 4;                    // cols 8..13
    int qg0 = qbase - 3 + s0; qg0 += (qg0 < 0) ? W_ : 0; qg0 -= (qg0 >= W_) ? W_ : 0;
    int qg1 = qbase - 3 + s1; qg1 += (qg1 < 0) ? W_ : 0; qg1 -= (qg1 >= W_) ? W_ : 0;
    const int colOff0 = qg0 * C_ + cbase + v0 * 4;
    const int colOff1 = qg1 * C_ + cbase + v0 * 4;
    // dst within a stage: col*256B + v*16B (second col is s0+8 -> +2048B)
    const uint32_t sdst = smem_u32(&sbuf[0][0][0]) + (uint32_t)(s0 * 256 + v0 * 16);

    // row cursor (circular over H, pointer-only)
    const float* const xBase = x + b * IMGSZ;
    const float* const xEnd  = xBase + IMGSZ;
    const float* rowPtr = xBase + (p0 - 3 < 0 ? p0 - 3 + H_ : p0 - 3) * ROWSZ;

    // ---- prologue: stage rows 0..5 into stages 0..5 (3 groups of 2 rows) ----
    #pragma unroll
    for (int pr = 0; pr < 3; ++pr) {
        uint32_t dA = sdst + (2 * pr) * STAGE_BYTES;
        cpasync16(dA, rowPtr + colOff0);
        if (has1) cpasync16(dA + 2048, rowPtr + colOff1);
        rowPtr += ROWSZ; if (rowPtr >= xEnd) rowPtr -= IMGSZ;
        uint32_t dB = sdst + (2 * pr + 1) * STAGE_BYTES;
        cpasync16(dB, rowPtr + colOff0);
        if (has1) cpasync16(dB + 2048, rowPtr + colOff1);
        rowPtr += ROWSZ; if (rowPtr >= xEnd) rowPtr -= IMGSZ;
        cp_commit();
    }

    // ring offsets: consume (two half-step cursors), prefetch dst
    uint32_t offCa = 0;
    uint32_t offCb = STAGE_BYTES;
    uint32_t offP  = 6 * STAGE_BYTES;

    // 7 rolling accumulators (static slots), f32x2 x NQ
    u64 acc[7][2];
    #pragma unroll
    for (int m = 0; m < 7; ++m) { acc[m][0] = 0ULL; acc[m][1] = 0ULL; }

    const int qOut = qbase + ty * NQ;
    int outOff = ((b * H_ + p0) * W_ + qOut) * C_ + c0;

    // ---- warm-up: rows t = 0..5 (no stores) ----
    MACRO2(0, 1, 0);
    MACRO2(2, 3, 0);
    MACRO2(4, 5, 0);

    // ---- main: rows t = 6..61, four 7-macro groups (I$-resident) ----
    #pragma unroll 1
    for (int o = 0; o < 4; ++o) {
        GROUP7M();
    }
}

extern "C" void kernel_launch(void* const* d_in, const int* in_sizes, int n_in,
                              void* d_out, int out_size) {
    const float* x    = (const float*)d_in[0];   // (8,224,224,192) fp32
    const float* kern = (const float*)d_in[1];   // (192,7,7) fp32
    float* out        = (float*)d_out;           // (8,224,224,192) fp32

    dim3 grid(W_ / QT, H_ / RH, B_ * 3);  // 28 x 4 x 24 = 2688 blocks
    dim3 block(PAIRS, QTH, 1);            // 128 threads
    dwconv_pipe2<<<grid, block>>>(x, kern, out);
}

// round 7
// speedup vs baseline: 3.2602x; 1.0248x over previous
#include <cuda_runtime.h>
#include <cstdint>

#define B_  8
#define H_  224
#define W_  224
#define C_  192
#define QT  8        // q positions per block
#define NQ  2        // q per thread
#define PAIRS 32     // channel pairs (threadIdx.x)
#define QTH  4       // q-thread groups (threadIdx.y)
#define NTHREADS 128
#define RH  56       // output rows per block
#define SROW 14      // staged columns per row (QT + 6)
#define STAGES 8
#define STAGE_BYTES (SROW * 64 * 4)          // 3584 B per stage
#define RING_BYTES  (STAGES * STAGE_BYTES)   // 28672 B
#define ROWSZ (W_ * C_)
#define IMGSZ (H_ * W_ * C_)

typedef unsigned long long u64;

__device__ __forceinline__ void fma2(u64 &d, u64 a, u64 b) {
    asm("fma.rn.f32x2 %0, %1, %2, %0;" : "+l"(d) : "l"(a), "l"(b));
}
__device__ __forceinline__ u64 pack2(float lo, float hi) {
    return (u64)__float_as_uint(lo) | ((u64)__float_as_uint(hi) << 32);
}
__device__ __forceinline__ void cpasync16(uint32_t dst, const float* src) {
    asm volatile("cp.async.cg.shared.global [%0], [%1], 16;" :: "r"(dst), "l"(src));
}
__device__ __forceinline__ void cp_commit() {
    asm volatile("cp.async.commit_group;" ::: "memory");
}
__device__ __forceinline__ void cp_wait2() {
    asm volatile("cp.async.wait_group 2;" ::: "memory");
}
__device__ __forceinline__ void cp_wait0() {
    asm volatile("cp.async.wait_group 0;" ::: "memory");
}
__device__ __forceinline__ uint32_t smem_u32(const void* p) {
    uint32_t a;
    asm("{ .reg .u64 t; cvta.to.shared.u64 t, %1; cvt.u32.u64 %0, t; }" : "=r"(a) : "l"(p));
    return a;
}

// Compute half-step at row phase T7 (t % 7), stage byte offset SOFF.
// Only kernel rows i in [ILO, IHI] are computed (compile-time pruned):
// output stored at step u receives row i = u - t from step t, so warm-up
// (t<6) skips i < 6-t and tail (t>55) skips i > 61-t -- exactly the
// contributions to never-stored rows. Slot (T7+2)%7 completes this step.
#define STEP_RANGE(T7, ILO, IHI, SOFF, DOSTORE) do {                          \
    const char* sb = (const char*)sbuf + (SOFF) + ty * (NQ * 256) + tx * 8;   \
    u64 w[8];                                                                 \
    _Pragma("unroll")                                                         \
    for (int d = 0; d < 8; ++d)                                               \
        w[d] = *(const u64*)(sb + d * 256);                                   \
    _Pragma("unroll")                                                         \
    for (int i = 0; i < 7; ++i) {                                             \
        if (i >= (ILO) && i <= (IHI)) {                                       \
            const int s = ((T7) + i + 2) % 7;                                 \
            _Pragma("unroll")                                                 \
            for (int j = 0; j < 7; ++j) {                                     \
                const u64 kv = kreg[i * 7 + j];                               \
                fma2(acc[s][0], kv, w[6 - j]);                                \
                fma2(acc[s][1], kv, w[7 - j]);                                \
            }                                                                 \
        }                                                                     \
    }                                                                         \
    {                                                                         \
        const int so = ((T7) + 2) % 7;                                        \
        if (DOSTORE) {                                                        \
            *(u64*)(out + outOff)      = acc[so][0];                          \
            *(u64*)(out + outOff + C_) = acc[so][1];                          \
            outOff += ROWSZ;                                                  \
        }                                                                     \
        acc[so][0] = 0ULL; acc[so][1] = 0ULL;                                 \
    }                                                                         \
} while (0)

// Macro step: one wait + one barrier + one commit group for TWO rows.
#define MACRO2R(T7a, LOa, T7b, LOb, DOSTORE) do {                             \
    cp_wait2();                                                               \
    __syncthreads();                                                          \
    {                                                                         \
        const uint32_t dA = sdst + offP;                                      \
        cpasync16(dA, rowPtr + colOff0);                                      \
        if (has1) cpasync16(dA + 2048, rowPtr + colOff1);                     \
        rowPtr += ROWSZ; if (rowPtr >= xEnd) rowPtr -= IMGSZ;                 \
        uint32_t p2 = offP + STAGE_BYTES;                                     \
        if (p2 >= RING_BYTES) p2 -= RING_BYTES;                               \
        const uint32_t dB = sdst + p2;                                        \
        cpasync16(dB, rowPtr + colOff0);                                      \
        if (has1) cpasync16(dB + 2048, rowPtr + colOff1);                     \
        rowPtr += ROWSZ; if (rowPtr >= xEnd) rowPtr -= IMGSZ;                 \
        cp_commit();                                                          \
        offP += 2 * STAGE_BYTES; if (offP >= RING_BYTES) offP -= RING_BYTES;  \
    }                                                                         \
    STEP_RANGE(T7a, LOa, 6, offCa, DOSTORE);                                  \
    offCa += 2 * STAGE_BYTES; if (offCa >= RING_BYTES) offCa -= RING_BYTES;   \
    STEP_RANGE(T7b, LOb, 6, offCb, DOSTORE);                                  \
    offCb += 2 * STAGE_BYTES; if (offCb >= RING_BYTES) offCb -= RING_BYTES;   \
} while (0)

// 7 macro steps = 14 rows: acc phase (mod 7) and ring phase repeat.
#define GROUP7M()                                                             \
    MACRO2R(6, 0, 0, 0, 1); MACRO2R(1, 0, 2, 0, 1); MACRO2R(3, 0, 4, 0, 1);   \
    MACRO2R(5, 0, 6, 0, 1); MACRO2R(0, 0, 1, 0, 1); MACRO2R(2, 0, 3, 0, 1);   \
    MACRO2R(4, 0, 5, 0, 1)

#define TAILSTEP(T7, IHI, CUR) do {                                           \
    STEP_RANGE(T7, 0, IHI, CUR, 1);                                           \
    CUR += 2 * STAGE_BYTES; if (CUR >= RING_BYTES) CUR -= RING_BYTES;         \
} while (0)

__global__ void __launch_bounds__(NTHREADS, 3)
dwconv_pipe3(const float* __restrict__ x, const float* __restrict__ kern,
             float* __restrict__ out)
{
    __shared__ float sbuf[STAGES][SROW][64];   // 28,672 B (8-stage ring)

    const int tx  = threadIdx.x;           // channel pair 0..31
    const int ty  = threadIdx.y;           // q group 0..3
    const int tid = ty * PAIRS + tx;

    const int wt = blockIdx.x;              // 0..27
    const int ht = blockIdx.y;              // 0..3
    const int bz = blockIdx.z;              // 0..23
    const int b  = bz / 3;
    const int g  = bz % 3;

    const int qbase = wt * QT;
    const int p0    = ht * RH;              // p0 % 7 == 0
    const int cbase = g * 64;
    const int c0    = cbase + 2 * tx;

    // ---- 49 kernel taps for this channel pair -> registers (f32x2) ----
    u64 kreg[49];
    #pragma unroll
    for (int t = 0; t < 49; ++t)
        kreg[t] = pack2(kern[c0 * 49 + t], kern[(c0 + 1) * 49 + t]);

    // ---- cp.async staging plan: 224 float4 per stage, threads 0..95 take 2 ----
    const int s0 = tid >> 4, v0 = tid & 15;             // cols 0..7
    const bool has1 = tid < 96;
    const int s1 = (tid + 128) >> 4;                    // cols 8..13
    int qg0 = qbase - 3 + s0; qg0 += (qg0 < 0) ? W_ : 0; qg0 -= (qg0 >= W_) ? W_ : 0;
    int qg1 = qbase - 3 + s1; qg1 += (qg1 < 0) ? W_ : 0; qg1 -= (qg1 >= W_) ? W_ : 0;
    const int colOff0 = qg0 * C_ + cbase + v0 * 4;
    const int colOff1 = qg1 * C_ + cbase + v0 * 4;
    const uint32_t sdst = smem_u32(&sbuf[0][0][0]) + (uint32_t)(s0 * 256 + v0 * 16);

    // row cursor (circular over H, pointer-only)
    const float* const xBase = x + b * IMGSZ;
    const float* const xEnd  = xBase + IMGSZ;
    const float* rowPtr = xBase + (p0 - 3 < 0 ? p0 - 3 + H_ : p0 - 3) * ROWSZ;

    // ---- prologue: stage rows 0..5 into stages 0..5 (3 groups of 2 rows) ----
    #pragma unroll
    for (int pr = 0; pr < 3; ++pr) {
        uint32_t dA = sdst + (2 * pr) * STAGE_BYTES;
        cpasync16(dA, rowPtr + colOff0);
        if (has1) cpasync16(dA + 2048, rowPtr + colOff1);
        rowPtr += ROWSZ; if (rowPtr >= xEnd) rowPtr -= IMGSZ;
        uint32_t dB = sdst + (2 * pr + 1) * STAGE_BYTES;
        cpasync16(dB, rowPtr + colOff0);
        if (has1) cpasync16(dB + 2048, rowPtr + colOff1);
        rowPtr += ROWSZ; if (rowPtr >= xEnd) rowPtr -= IMGSZ;
        cp_commit();
    }

    uint32_t offCa = 0;
    uint32_t offCb = STAGE_BYTES;
    uint32_t offP  = 6 * STAGE_BYTES;

    // 7 rolling accumulators (static slots), f32x2 x NQ
    u64 acc[7][2];
    #pragma unroll
    for (int m = 0; m < 7; ++m) { acc[m][0] = 0ULL; acc[m][1] = 0ULL; }

    const int qOut = qbase + ty * NQ;
    int outOff = ((b * H_ + p0) * W_ + qOut) * C_ + c0;

    // ---- warm-up: rows t = 0..5, wedge-pruned (i >= 6-t), no stores ----
    MACRO2R(0, 6, 1, 5, 0);
    MACRO2R(2, 4, 3, 3, 0);
    MACRO2R(4, 2, 5, 1, 0);

    // ---- main: rows t = 6..47, three 7-macro groups (I$-resident) ----
    #pragma unroll 1
    for (int o = 0; o < 3; ++o) {
        GROUP7M();
    }
    // ---- main remainder: rows t = 48..55 ----
    MACRO2R(6, 0, 0, 0, 1);
    MACRO2R(1, 0, 2, 0, 1);
    MACRO2R(3, 0, 4, 0, 1);
    MACRO2R(5, 0, 6, 0, 1);

    // ---- tail: rows t = 56..61, wedge-pruned (i <= 61-t), all data resident ----
    cp_wait0();
    __syncthreads();
    TAILSTEP(0, 5, offCa);
    TAILSTEP(1, 4, offCb);
    TAILSTEP(2, 3, offCa);
    TAILSTEP(3, 2, offCb);
    TAILSTEP(4, 1, offCa);
    TAILSTEP(5, 0, offCb);
}

extern "C" void kernel_launch(void* const* d_in, const int* in_sizes, int n_in,
                              void* d_out, int out_size) {
    const float* x    = (const float*)d_in[0];   // (8,224,224,192) fp32
    const float* kern = (const float*)d_in[1];   // (192,7,7) fp32
    float* out        = (float*)d_out;           // (8,224,224,192) fp32

    dim3 grid(W_ / QT, H_ / RH, B_ * 3);  // 28 x 4 x 24 = 2688 blocks
    dim3 block(PAIRS, QTH, 1);            // 128 threads
    dwconv_pipe3<<<grid, block>>>(x, kern, out);
}